// round 7
// baseline (speedup 1.0000x reference)
#include <cuda_runtime.h>
#include <math.h>

#define AEMB 16
#define DIN  480
#define NTH  512
#define BM   128

// ---- shared memory layout (float offsets) ----
#define X0_PITCH 129
#define AS_PITCH 17
#define AS_OFF   (BM * X0_PITCH)            // 16512
#define B1_OFF   (AS_OFF + BM * AS_PITCH)   // 18688
#define B2_OFF   (B1_OFF + 128)             // 18816
#define WB_OFF   (B2_OFF + 16)              // 18832 (16B-aligned: *4)
#define WBUF     8256                       // 8 kc-blocks * 1032 (1024 + 8 skew)
#define MID_OFF  (WB_OFF + 2 * WBUF)        // 35344
#define SMEM_FLOATS (MID_OFF + BM * 17)     // 37520
#define SMEM_BYTES  (SMEM_FLOATS * 4)       // 150080

__device__ __forceinline__ unsigned cvt_tf32(float f) {
    unsigned u; asm("cvt.rna.tf32.f32 %0, %1;" : "=r"(u) : "f"(f)); return u;
}
__device__ __forceinline__ void mma_tf32(float* d, unsigned a0, unsigned a1,
                                         unsigned a2, unsigned a3,
                                         unsigned b0, unsigned b1) {
    asm volatile(
        "mma.sync.aligned.m16n8k8.row.col.f32.tf32.tf32.f32 "
        "{%0,%1,%2,%3}, {%4,%5,%6,%7}, {%8,%9}, {%0,%1,%2,%3};"
        : "+f"(d[0]), "+f"(d[1]), "+f"(d[2]), "+f"(d[3])
        : "r"(a0), "r"(a1), "r"(a2), "r"(a3), "r"(b0), "r"(b1));
}
__device__ __forceinline__ float silu_f(float x) { return x / (1.0f + __expf(-x)); }

__global__ void __launch_bounds__(NTH, 1)
tp_head_kernel(const float* __restrict__ nv, const float* __restrict__ ae,
               const float* __restrict__ W1, const float* __restrict__ b1,
               const float* __restrict__ W2, const float* __restrict__ b2,
               const float* __restrict__ W3, const float* __restrict__ b3,
               const float* __restrict__ W4, const float* __restrict__ b4,
               float* __restrict__ out)
{
    extern __shared__ float sm[];
    float* x0s  = sm;                 // [128][129] x0, later scalars
    float* as_  = sm + AS_OFF;        // [128][17]
    float* b1s  = sm + B1_OFF;
    float* b2s  = sm + B2_OFF;
    float* wb   = sm + WB_OFF;        // 2 x WBUF B-staging buffers
    float* mids = sm + MID_OFF;       // [128][17]

    const int tid = threadIdx.x;
    const int wid = tid >> 5;
    const int l   = tid & 31;
    const int n0  = blockIdx.x * BM;
    const int q   = l >> 2;           // 0..7
    const int lk  = l & 3;            // 0..3

    // ---- stage x0 (first 128 cols), a, b1, b2 ----
    for (int t = tid; t < BM * 32; t += NTH) {
        int lr = t >> 5, c4 = (t & 31) << 2;
        float4 v = *(const float4*)(nv + (size_t)(n0 + lr) * DIN + c4);
        float* dst = x0s + lr * X0_PITCH + c4;
        dst[0] = v.x; dst[1] = v.y; dst[2] = v.z; dst[3] = v.w;
    }
    {
        int lr = tid >> 2, c4 = (tid & 3) << 2;  // 512 = 128*4 exactly
        float4 v = *(const float4*)(ae + (size_t)(n0 + lr) * AEMB + c4);
        float* dst = as_ + lr * AS_PITCH + c4;
        dst[0] = v.x; dst[1] = v.y; dst[2] = v.z; dst[3] = v.w;
    }
    if (tid < 128) b1s[tid] = b1[tid];
    if (tid >= 128 && tid < 144) b2s[tid - 128] = b2[tid - 128];

    // ---- phase-1 staging thread mapping ----
    const int cg1 = tid >> 6;        // column group (16 cols), = tp
    const int kl1 = tid & 63;        // k-row within 64-chunk
    const int kc1 = kl1 >> 3, kr1 = kl1 & 7;
    const int lk1 = kr1 & 3, hf1 = kr1 >> 2;
    float* st1base = wb + kc1 * 1032 + cg1 * 128;

    float4 wreg[4];
    {   // prefetch chunk 0
        const float* src = W1 + ((size_t)((kl1 >> 4) * 16 + (kl1 & 15))) * 224 + cg1 * 16;
#pragma unroll
        for (int j = 0; j < 4; ++j) wreg[j] = ((const float4*)src)[j];
    }
    __syncthreads();

    // ---- per-warp MMA geometry: 32 rows (2 strips) x 4 tiles ----
    const int rp = wid >> 2;          // row-pair 0..3 -> rows [rp*32, rp*32+32)
    const int nq = wid & 3;           // tile quad: tiles nq*4..nq*4+3
    float ar[4][4];                   // a[row_j, {lk, lk+4, 8+lk, 12+lk}]
#pragma unroll
    for (int j = 0; j < 4; ++j) {
        int rj = rp * 32 + q + j * 8;
        ar[j][0] = as_[rj * AS_PITCH + lk];
        ar[j][1] = as_[rj * AS_PITCH + lk + 4];
        ar[j][2] = as_[rj * AS_PITCH + lk + 8];
        ar[j][3] = as_[rj * AS_PITCH + lk + 12];
    }

    float acc[8][4];                  // [strip*4 + tile][frag]
#pragma unroll
    for (int t = 0; t < 8; ++t)
#pragma unroll
        for (int e = 0; e < 4; ++e) acc[t][e] = 0.0f;

    // =================== Phase 1: s = (x0 (x) a) @ W1flat ===================
    for (int sc = 0; sc < 32; ++sc) {
        {   // store wreg (chunk sc) -> buf, conflict-free skewed layout
            float* b = st1base + (sc & 1) * WBUF;
            const float* w = (const float*)wreg;
#pragma unroll
            for (int e = 0; e < 16; ++e)
                *(unsigned*)(b + ((e & 7) * 4 + lk1) * 4 + (e >> 3) * 2 + hf1) =
                    cvt_tf32(w[e]);
        }
        if (sc + 1 < 32) {  // prefetch chunk sc+1
            const float* src = W1 +
                ((size_t)(((sc + 1) * 4 + (kl1 >> 4)) * 16 + (kl1 & 15))) * 224 + cg1 * 16;
#pragma unroll
            for (int j = 0; j < 4; ++j) wreg[j] = ((const float4*)src)[j];
        }
        __syncthreads();

        const float* bbase = wb + (sc & 1) * WBUF;
        float xv[4];
#pragma unroll
        for (int kc = 0; kc < 8; ++kc) {
            if ((kc & 1) == 0) {
                int i = sc * 4 + (kc >> 1);
#pragma unroll
                for (int j = 0; j < 4; ++j)
                    xv[j] = x0s[(rp * 32 + q + j * 8) * X0_PITCH + i];
            }
            const int idx0 = (kc & 1) * 2;
            unsigned A0[4], A1[4];
            A0[0] = cvt_tf32(xv[0] * ar[0][idx0]);
            A0[1] = cvt_tf32(xv[1] * ar[1][idx0]);
            A0[2] = cvt_tf32(xv[0] * ar[0][idx0 + 1]);
            A0[3] = cvt_tf32(xv[1] * ar[1][idx0 + 1]);
            A1[0] = cvt_tf32(xv[2] * ar[2][idx0]);
            A1[1] = cvt_tf32(xv[3] * ar[3][idx0]);
            A1[2] = cvt_tf32(xv[2] * ar[2][idx0 + 1]);
            A1[3] = cvt_tf32(xv[3] * ar[3][idx0 + 1]);
#pragma unroll
            for (int j = 0; j < 2; ++j) {
                float4 bv = *((const float4*)(bbase + kc * 1032 + (nq * 2 + j) * 128) + l);
                unsigned b00 = __float_as_uint(bv.x), b01 = __float_as_uint(bv.y);
                unsigned b10 = __float_as_uint(bv.z), b11 = __float_as_uint(bv.w);
                mma_tf32(acc[j * 2 + 0],     A0[0], A0[1], A0[2], A0[3], b00, b01);
                mma_tf32(acc[j * 2 + 1],     A0[0], A0[1], A0[2], A0[3], b10, b11);
                mma_tf32(acc[4 + j * 2 + 0], A1[0], A1[1], A1[2], A1[3], b00, b01);
                mma_tf32(acc[4 + j * 2 + 1], A1[0], A1[1], A1[2], A1[3], b10, b11);
            }
        }
    }
    __syncthreads();   // all warps done reading x0s before scalars overwrite it

    // ---- epilogue 1: scalars = silu(s*INV + b1) -> x0s ----
    const float INV = 0.022097086912079608f;   // 1/sqrt(128*16)
#pragma unroll
    for (int st = 0; st < 2; ++st)
#pragma unroll
        for (int tt = 0; tt < 4; ++tt) {
            int c0 = (nq * 4 + tt) * 8 + lk * 2;
            int row = rp * 32 + st * 16 + q;
            float* a = acc[st * 4 + tt];
            x0s[row * X0_PITCH + c0]           = silu_f(a[0] * INV + b1s[c0]);
            x0s[row * X0_PITCH + c0 + 1]       = silu_f(a[1] * INV + b1s[c0 + 1]);
            x0s[(row + 8) * X0_PITCH + c0]     = silu_f(a[2] * INV + b1s[c0]);
            x0s[(row + 8) * X0_PITCH + c0 + 1] = silu_f(a[3] * INV + b1s[c0 + 1]);
        }

    // ---- phase-2 staging mapping (chunks of 256 k-rows, 8 chunks) ----
    const int cg2 = tid >> 8;         // 0..1 (8 cols each)
    const int kl2 = tid & 255;
    const int kc2 = kl2 >> 3, kr2 = kl2 & 7;
    const int lk2 = kr2 & 3, hf2 = kr2 >> 2;
    float4 w2reg[2];
    {   // prefetch chunk 0
        const float* src = W2 + ((size_t)((kl2 >> 4) * 16 + (kl2 & 15))) * 16 + cg2 * 8;
        w2reg[0] = ((const float4*)src)[0];
        w2reg[1] = ((const float4*)src)[1];
    }
    __syncthreads();

    // ---- phase-2 MMA geometry: 16 rows x 1 tile per warp ----
    const int sW = wid >> 1;          // strip 0..7
    const int th = wid & 1;           // tile 0..1
    float ar2[2][4];
#pragma unroll
    for (int j = 0; j < 2; ++j) {
        int rj = sW * 16 + q + j * 8;
        ar2[j][0] = as_[rj * AS_PITCH + lk];
        ar2[j][1] = as_[rj * AS_PITCH + lk + 4];
        ar2[j][2] = as_[rj * AS_PITCH + lk + 8];
        ar2[j][3] = as_[rj * AS_PITCH + lk + 12];
    }
    float acc2[4] = {0.0f, 0.0f, 0.0f, 0.0f};

    for (int cN = 0; cN < 8; ++cN) {
        {   // store chunk cN
            float* b = wb + (cN & 1) * WBUF + kc2 * 136;
            const float* w = (const float*)w2reg;
#pragma unroll
            for (int e = 0; e < 8; ++e)
                *(unsigned*)(b + (e * 4 + lk2) * 4 + cg2 * 2 + hf2) = cvt_tf32(w[e]);
        }
        if (cN + 1 < 8) {
            const float* src = W2 +
                ((size_t)(((cN + 1) * 16 + (kl2 >> 4)) * 16 + (kl2 & 15))) * 16 + cg2 * 8;
            w2reg[0] = ((const float4*)src)[0];
            w2reg[1] = ((const float4*)src)[1];
        }
        __syncthreads();

        const float* bbase = wb + (cN & 1) * WBUF;
        float xv2[2];
#pragma unroll 8
        for (int kc = 0; kc < 32; ++kc) {
            if ((kc & 1) == 0) {
                int i = cN * 16 + (kc >> 1);
                xv2[0] = x0s[(sW * 16 + q) * X0_PITCH + i];
                xv2[1] = x0s[(sW * 16 + 8 + q) * X0_PITCH + i];
            }
            const int idx0 = (kc & 1) * 2;
            unsigned a0 = cvt_tf32(xv2[0] * ar2[0][idx0]);
            unsigned a1 = cvt_tf32(xv2[1] * ar2[1][idx0]);
            unsigned a2 = cvt_tf32(xv2[0] * ar2[0][idx0 + 1]);
            unsigned a3 = cvt_tf32(xv2[1] * ar2[1][idx0 + 1]);
            float2 bv = *(const float2*)(bbase + kc * 136 + l * 4 + th * 2);
            mma_tf32(acc2, a0, a1, a2, a3,
                     __float_as_uint(bv.x), __float_as_uint(bv.y));
        }
    }
    // epilogue 2
    {
        int c0 = th * 8 + lk * 2;
        int row = sW * 16 + q;
        mids[row * 17 + c0]           = acc2[0] * INV + b2s[c0];
        mids[row * 17 + c0 + 1]       = acc2[1] * INV + b2s[c0 + 1];
        mids[(row + 8) * 17 + c0]     = acc2[2] * INV + b2s[c0];
        mids[(row + 8) * 17 + c0 + 1] = acc2[3] * INV + b2s[c0 + 1];
    }
    __syncthreads();

    // stage W3/W4/b3/b4 into wb (free now)
    if (tid < 256) wb[tid] = W3[tid];
    if (tid >= 256 && tid < 272) wb[tid] = W4[tid - 256];
    if (tid >= 288 && tid < 304) wb[tid] = b3[tid - 288];
    if (tid == 304) wb[304] = b4[0];
    __syncthreads();

    // =================== Phase 3: tiny 16x16 head ===================
    if (tid < BM) {
        float mv[16];
#pragma unroll
        for (int j = 0; j < 16; ++j) mv[j] = mids[tid * 17 + j];
        float o = 0.0f;
#pragma unroll
        for (int jo = 0; jo < 16; ++jo) {
            float t = 0.0f;
#pragma unroll
            for (int ji = 0; ji < 16; ++ji) t += mv[ji] * wb[ji * 16 + jo];
            t = t * 0.25f + wb[288 + jo];
            o += silu_f(t) * wb[256 + jo];
        }
        out[n0 + tid] = o * 0.25f + wb[304];
    }
}

extern "C" void kernel_launch(void* const* d_in, const int* in_sizes, int n_in,
                              void* d_out, int out_size) {
    const float* nv = (const float*)d_in[0];
    const float* ae = (const float*)d_in[1];
    const float* W1 = (const float*)d_in[2];
    // d_in[3], d_in[4] dead (W1_l1, W1_l2)
    const float* b1 = (const float*)d_in[5];
    const float* W2 = (const float*)d_in[6];
    const float* b2 = (const float*)d_in[7];
    const float* W3 = (const float*)d_in[8];
    const float* b3 = (const float*)d_in[9];
    const float* W4 = (const float*)d_in[10];
    const float* b4 = (const float*)d_in[11];
    float* out = (float*)d_out;

    int nodes = in_sizes[1] / AEMB;
    int grid  = nodes / BM;

    cudaFuncSetAttribute(tp_head_kernel,
                         cudaFuncAttributeMaxDynamicSharedMemorySize, SMEM_BYTES);
    tp_head_kernel<<<grid, NTH, SMEM_BYTES>>>(nv, ae, W1, b1, W2, b2,
                                              W3, b3, W4, b4, out);
}